// round 2
// baseline (speedup 1.0000x reference)
#include <cuda_runtime.h>
#include <math.h>
#include <stdint.h>

#define TPB 128

// shared-memory float offsets
#define F_OFF     0        // 6*16*16  = 1536
#define RPAD_OFF  1536     // 6*14*14  = 1176 (max W2=14 for hw<=12)
#define HPAD_OFF  2712     // 48*14*14 = 9408
#define ZPART_OFF 12120    // 8*6*144  = 6912
#define ZBUF_OFF  19032    // 6*144    = 864
#define W1T_OFF   19896    // 54*48    = 2592  (16B aligned: 19896*4 % 16 == 0)
#define W2S_OFF   22488    // 432*8    = 3456  (16B aligned)
#define B1S_OFF   25944    // 48
#define B2S_OFF   25992    // 8
#define SMEM_FLOATS 26000
#define SMEM_BYTES (SMEM_FLOATS * 4)

__constant__ int      c_hw[8]   = {1, 2, 4, 6, 8, 10, 12, 16};
__constant__ int      c_off[8]  = {0, 6, 30, 126, 342, 726, 1326, 2190};
// ceil(2^32 / d); sentinel 0 for d==1 (special-cased)
__constant__ uint32_t c_mhw[8]  = {0u, 2147483648u, 1073741824u, 715827883u,
                                   536870912u, 429496730u, 357913942u, 268435456u};
__constant__ uint32_t c_mnpx[8] = {0u, 1073741824u, 268435456u, 119304648u,
                                   67108864u, 42949673u, 29826162u, 16777216u};

// XLA's fp32 tanh rational approximation (matches jax-emitted tanh)
__device__ __forceinline__ float tanh_xla(float x) {
    float cx = fminf(fmaxf(x, -7.90531110763549805f), 7.90531110763549805f);
    float x2 = cx * cx;
    float np_ = fmaf(-2.76076847742355e-16f, x2, 2.00018790482477e-13f);
    np_ = fmaf(np_, x2, -8.60467152213735e-11f);
    np_ = fmaf(np_, x2, 5.12229709037114e-08f);
    np_ = fmaf(np_, x2, 1.48572235717979e-05f);
    np_ = fmaf(np_, x2, 6.37261928875436e-04f);
    np_ = fmaf(np_, x2, 4.89352455891786e-03f);
    float num = cx * np_;
    float dp_ = fmaf(1.19825839466702e-06f, x2, 1.18534705686654e-04f);
    dp_ = fmaf(dp_, x2, 2.26843463243900e-03f);
    dp_ = fmaf(dp_, x2, 4.89352518554385e-03f);
    float r = num / dp_;
    return (fabsf(x) < 0.0004f) ? x : r;
}

__device__ __forceinline__ float gelu_exact(float h) {
    return 0.5f * h * (1.0f + erff(h * 0.70710678118654752f));
}

__global__ void __launch_bounds__(TPB, 2) var_tok_kernel(
    const float* __restrict__ latents, const float* __restrict__ w1,
    const float* __restrict__ b1, const float* __restrict__ w2,
    const float* __restrict__ b2, float* __restrict__ out)
{
    extern __shared__ float sm[];
    const int tid = threadIdx.x;

    // FSQ constants, computed exactly as the reference does in fp32
    const float halfl8 = (8.0f - 1.0f) * (1.0f + 1e-3f) / 2.0f;   // 3.5035
    const float shift8 = atanhf(0.5f / halfl8);
    const float halfl5 = (5.0f - 1.0f) * (1.0f + 1e-3f) / 2.0f;   // 2.002

    const float* lat = latents + (size_t)blockIdx.x * 1536;
    float* outb = out + (size_t)blockIdx.x * 3726;

    for (int i = tid; i < 1536; i += TPB) sm[F_OFF + i] = lat[i];

    for (int s = 0; s < 8; s++) {
        const int hw  = c_hw[s];
        const int npx = hw * hw;
        const int W2  = hw + 2;
        const int w22 = W2 * W2;
        const uint32_t mhw  = c_mhw[s];
        const uint32_t mnpx = c_mnpx[s];
        const bool last = (s == 7);

        // ---- stage 0: zero padded buffers, stage reordered weights ----
        if (!last) {
            for (int i = tid; i < 6 * w22;  i += TPB) sm[RPAD_OFF + i] = 0.0f;
            for (int i = tid; i < 48 * w22; i += TPB) sm[HPAD_OFF + i] = 0.0f;
            const float* w1g = w1 + s * 2592;      // [48][6*9]
            for (int i = tid; i < 2592; i += TPB) {
                int oc = i / 54; int j = i - oc * 54;
                sm[W1T_OFF + j * 48 + oc] = w1g[i]; // -> [54][48]
            }
            const float* w2g = w2 + s * 2592;      // [6][48*9]
            for (int i = tid; i < 2592; i += TPB) {
                int oc = i / 432; int j = i - oc * 432;
                sm[W2S_OFF + j * 8 + oc] = w2g[i];  // -> [432][8pad]
            }
            if (tid < 48) sm[B1S_OFF + tid] = b1[s * 48 + tid];
            if (tid < 6)  sm[B2S_OFF + tid] = b2[s * 6 + tid];
        }
        __syncthreads();

        // ---- Phase A: bilinear downsample f -> FSQ quantize -> out (+ rpad interior) ----
        {
            const float sc = 16.0f / (float)hw;
            float* ob = outb + c_off[s];
            const int n = 6 * npx;
            for (int idx = tid; idx < n; idx += TPB) {
                int c, p;
                if (npx == 1) { c = idx; p = 0; }
                else { c = (int)__umulhi((unsigned)idx, mnpx); p = idx - c * npx; }
                int oy, ox;
                if (hw == 1) { oy = 0; ox = 0; }
                else { oy = (int)__umulhi((unsigned)p, mhw); ox = p - oy * hw; }
                float sy = __fadd_rn(__fmul_rn((float)oy + 0.5f, sc), -0.5f);
                float sx = __fadd_rn(__fmul_rn((float)ox + 0.5f, sc), -0.5f);
                float fy = floorf(sy), fx = floorf(sx);
                float wy = sy - fy,  wx = sx - fx;
                int y0 = (int)fy, x0 = (int)fx;
                int ya = min(max(y0, 0), 15),     yb = min(max(y0 + 1, 0), 15);
                int xa = min(max(x0, 0), 15),     xb = min(max(x0 + 1, 0), 15);
                const float* fc = sm + F_OFF + (c << 8);
                float v00 = fc[ya * 16 + xa], v01 = fc[ya * 16 + xb];
                float v10 = fc[yb * 16 + xa], v11 = fc[yb * 16 + xb];
                float va = __fadd_rn(__fmul_rn(v00, 1.0f - wx), __fmul_rn(v01, wx));
                float vb = __fadd_rn(__fmul_rn(v10, 1.0f - wx), __fmul_rn(v11, wx));
                float v  = __fadd_rn(__fmul_rn(va, 1.0f - wy), __fmul_rn(vb, wy));
                float q;
                if (c < 3) {
                    float bnd = __fadd_rn(__fmul_rn(tanh_xla(v + shift8), halfl8), -0.5f);
                    q = rintf(bnd) * 0.25f;
                } else {
                    float bnd = __fmul_rn(tanh_xla(v), halfl5);
                    q = rintf(bnd) * 0.5f;
                }
                ob[idx] = q;
                if (!last) sm[RPAD_OFF + c * w22 + (oy + 1) * W2 + (ox + 1)] = q;
            }
        }
        if (last) break;
        __syncthreads();

        // ---- conv1 (6->48) + GELU: tasks = (pixel, oc-group-of-4) ----
        {
            const int ntask = 12 * npx;
            for (int t = tid; t < ntask; t += TPB) {
                int g, p;
                if (npx == 1) { g = t; p = 0; }
                else { g = (int)__umulhi((unsigned)t, mnpx); p = t - g * npx; }
                int y, x;
                if (hw == 1) { y = 0; x = 0; }
                else { y = (int)__umulhi((unsigned)p, mhw); x = p - y * hw; }
                float a0 = 0.f, a1 = 0.f, a2 = 0.f, a3 = 0.f;
                const float* wbase = sm + W1T_OFF + g * 4;
                for (int ic = 0; ic < 6; ic++) {
                    const float* rrow = sm + RPAD_OFF + ic * w22 + y * W2 + x;
                    const float* wr = wbase + ic * 9 * 48;
                    #pragma unroll
                    for (int ky = 0; ky < 3; ky++) {
                        #pragma unroll
                        for (int kx = 0; kx < 3; kx++) {
                            float v = rrow[ky * W2 + kx];
                            float4 w = *(const float4*)(wr + (ky * 3 + kx) * 48);
                            a0 = fmaf(v, w.x, a0);
                            a1 = fmaf(v, w.y, a1);
                            a2 = fmaf(v, w.z, a2);
                            a3 = fmaf(v, w.w, a3);
                        }
                    }
                }
                int hp = HPAD_OFF + (y + 1) * W2 + (x + 1);
                int oc0 = g * 4;
                sm[hp + (oc0 + 0) * w22] = gelu_exact(a0 + sm[B1S_OFF + oc0 + 0]);
                sm[hp + (oc0 + 1) * w22] = gelu_exact(a1 + sm[B1S_OFF + oc0 + 1]);
                sm[hp + (oc0 + 2) * w22] = gelu_exact(a2 + sm[B1S_OFF + oc0 + 2]);
                sm[hp + (oc0 + 3) * w22] = gelu_exact(a3 + sm[B1S_OFF + oc0 + 3]);
            }
        }
        __syncthreads();

        // ---- conv2 (48->6) partials: tasks = (pixel, ic-group-of-6) ----
        {
            const int ntask = 8 * npx;
            for (int t = tid; t < ntask; t += TPB) {
                int g, p;
                if (npx == 1) { g = t; p = 0; }
                else { g = (int)__umulhi((unsigned)t, mnpx); p = t - g * npx; }
                int y, x;
                if (hw == 1) { y = 0; x = 0; }
                else { y = (int)__umulhi((unsigned)p, mhw); x = p - y * hw; }
                float a0 = 0.f, a1 = 0.f, a2 = 0.f, a3 = 0.f, a4 = 0.f, a5 = 0.f;
                for (int icl = 0; icl < 6; icl++) {
                    int ic = g * 6 + icl;
                    const float* hrow = sm + HPAD_OFF + ic * w22 + y * W2 + x;
                    const float* wr = sm + W2S_OFF + ic * 9 * 8;
                    #pragma unroll
                    for (int ky = 0; ky < 3; ky++) {
                        #pragma unroll
                        for (int kx = 0; kx < 3; kx++) {
                            float v = hrow[ky * W2 + kx];
                            const float* wk = wr + (ky * 3 + kx) * 8;
                            float4 wa = *(const float4*)(wk);
                            float2 wb = *(const float2*)(wk + 4);
                            a0 = fmaf(v, wa.x, a0); a1 = fmaf(v, wa.y, a1);
                            a2 = fmaf(v, wa.z, a2); a3 = fmaf(v, wa.w, a3);
                            a4 = fmaf(v, wb.x, a4); a5 = fmaf(v, wb.y, a5);
                        }
                    }
                }
                float* zp = sm + ZPART_OFF + g * 6 * npx + p;
                zp[0]       = a0; zp[npx]     = a1; zp[2 * npx] = a2;
                zp[3 * npx] = a3; zp[4 * npx] = a4; zp[5 * npx] = a5;
            }
        }
        __syncthreads();

        // ---- reduce partials + bias -> zbuf ----
        {
            const int n = 6 * npx;
            for (int t = tid; t < n; t += TPB) {
                int oc, p;
                if (npx == 1) { oc = t; p = 0; }
                else { oc = (int)__umulhi((unsigned)t, mnpx); p = t - oc * npx; }
                float sum = sm[B2S_OFF + oc];
                #pragma unroll
                for (int g = 0; g < 8; g++) sum += sm[ZPART_OFF + (g * 6 + oc) * npx + p];
                sm[ZBUF_OFF + oc * npx + p] = sum;
            }
        }
        __syncthreads();

        // ---- bilinear upsample zbuf -> 16x16, subtract from f ----
        {
            const float sc2 = (float)hw / 16.0f;
            const int hm = hw - 1;
            for (int idx = tid; idx < 1536; idx += TPB) {
                int c = idx >> 8, p = idx & 255;
                int oy = p >> 4, ox = p & 15;
                float sy = __fadd_rn(__fmul_rn((float)oy + 0.5f, sc2), -0.5f);
                float sx = __fadd_rn(__fmul_rn((float)ox + 0.5f, sc2), -0.5f);
                float fy = floorf(sy), fx = floorf(sx);
                float wy = sy - fy,  wx = sx - fx;
                int y0 = (int)fy, x0 = (int)fx;
                int ya = min(max(y0, 0), hm), yb = min(max(y0 + 1, 0), hm);
                int xa = min(max(x0, 0), hm), xb = min(max(x0 + 1, 0), hm);
                const float* zc = sm + ZBUF_OFF + c * npx;
                float v00 = zc[ya * hw + xa], v01 = zc[ya * hw + xb];
                float v10 = zc[yb * hw + xa], v11 = zc[yb * hw + xb];
                float va = __fadd_rn(__fmul_rn(v00, 1.0f - wx), __fmul_rn(v01, wx));
                float vb = __fadd_rn(__fmul_rn(v10, 1.0f - wx), __fmul_rn(v11, wx));
                float v  = __fadd_rn(__fmul_rn(va, 1.0f - wy), __fmul_rn(vb, wy));
                sm[F_OFF + idx] -= v;
            }
        }
        __syncthreads();
    }
}

extern "C" void kernel_launch(void* const* d_in, const int* in_sizes, int n_in,
                              void* d_out, int out_size) {
    const float* latents = (const float*)d_in[0];
    const float* w1 = (const float*)d_in[1];
    const float* b1 = (const float*)d_in[2];
    const float* w2 = (const float*)d_in[3];
    const float* b2 = (const float*)d_in[4];
    float* out = (float*)d_out;
    int B = in_sizes[0] / 1536;
    cudaFuncSetAttribute(var_tok_kernel,
                         cudaFuncAttributeMaxDynamicSharedMemorySize, SMEM_BYTES);
    var_tok_kernel<<<B, TPB, SMEM_BYTES>>>(latents, w1, b1, w2, b2, out);
}

// round 7
// speedup vs baseline: 1.1523x; 1.1523x over previous
#include <cuda_runtime.h>
#include <math.h>
#include <stdint.h>

#define TPB 128

// shared-memory float offsets (same layout as the passing R2 kernel)
#define F_OFF     0        // 6*16*16  = 1536
#define RPAD_OFF  1536     // 6*14*14  = 1176
#define HPAD_OFF  2712     // 48*14*14 = 9408
#define ZPART_OFF 12120    // 8*6*144  = 6912
#define ZBUF_OFF  19032    // 6*144    = 864
#define W1T_OFF   19896    // 54*48    = 2592  (16B aligned)
#define W2S_OFF   22488    // 432*8    = 3456  (16B aligned)
#define B1S_OFF   25944    // 48
#define B2S_OFF   25992    // 8
#define SMEM_FLOATS 26000
#define SMEM_BYTES (SMEM_FLOATS * 4)

__constant__ int      c_hw[8]   = {1, 2, 4, 6, 8, 10, 12, 16};
__constant__ int      c_off[8]  = {0, 6, 30, 126, 342, 726, 1326, 2190};
// ceil(2^32/d); sentinel 0 for d==1
__constant__ uint32_t c_mhw[8]  = {0u, 2147483648u, 1073741824u, 715827883u,
                                   536870912u, 429496730u, 357913942u, 268435456u};
__constant__ uint32_t c_mnpx[8] = {0u, 1073741824u, 268435456u, 119304648u,
                                   67108864u, 42949673u, 29826162u, 16777216u};
// nq = npx/2: {-,2,8,18,32,50,72,-}
__constant__ uint32_t c_mnq[8]  = {0u, 2147483648u, 536870912u, 238609295u,
                                   134217728u, 85899346u, 59652324u, 0u};

// XLA's fp32 tanh rational approximation
__device__ __forceinline__ float tanh_xla(float x) {
    float cx = fminf(fmaxf(x, -7.90531110763549805f), 7.90531110763549805f);
    float x2 = cx * cx;
    float np_ = fmaf(-2.76076847742355e-16f, x2, 2.00018790482477e-13f);
    np_ = fmaf(np_, x2, -8.60467152213735e-11f);
    np_ = fmaf(np_, x2, 5.12229709037114e-08f);
    np_ = fmaf(np_, x2, 1.48572235717979e-05f);
    np_ = fmaf(np_, x2, 6.37261928875436e-04f);
    np_ = fmaf(np_, x2, 4.89352455891786e-03f);
    float num = cx * np_;
    float dp_ = fmaf(1.19825839466702e-06f, x2, 1.18534705686654e-04f);
    dp_ = fmaf(dp_, x2, 2.26843463243900e-03f);
    dp_ = fmaf(dp_, x2, 4.89352518554385e-03f);
    float r = num / dp_;
    return (fabsf(x) < 0.0004f) ? x : r;
}

__device__ __forceinline__ float gelu_exact(float h) {
    return 0.5f * h * (1.0f + erff(h * 0.70710678118654752f));
}

__global__ void __launch_bounds__(TPB) var_tok_kernel(
    const float* __restrict__ latents, const float* __restrict__ w1,
    const float* __restrict__ b1, const float* __restrict__ w2,
    const float* __restrict__ b2, float* __restrict__ out)
{
    extern __shared__ float sm[];
    const int tid = threadIdx.x;

    const float halfl8 = (8.0f - 1.0f) * (1.0f + 1e-3f) / 2.0f;
    const float shift8 = atanhf(0.5f / halfl8);
    const float halfl5 = (5.0f - 1.0f) * (1.0f + 1e-3f) / 2.0f;

    const float* lat = latents + (size_t)blockIdx.x * 1536;
    float* outb = out + (size_t)blockIdx.x * 3726;

    for (int i = tid; i < 1536; i += TPB) sm[F_OFF + i] = lat[i];

    for (int s = 0; s < 8; s++) {
        const int hw  = c_hw[s];
        const int npx = hw * hw;
        const int W2  = hw + 2;
        const int w22 = W2 * W2;
        const uint32_t mhw  = c_mhw[s];
        const uint32_t mnpx = c_mnpx[s];
        const bool last = (s == 7);

        // ---- stage 0: zero padded buffers, stage reordered weights ----
        if (!last) {
            if (hw > 1) {
                for (int i = tid; i < 6 * w22;  i += TPB) sm[RPAD_OFF + i] = 0.0f;
                for (int i = tid; i < 48 * w22; i += TPB) sm[HPAD_OFF + i] = 0.0f;
            }
            const float* w1g = w1 + s * 2592;       // [48][54]
            for (int i = tid; i < 2592; i += TPB) {
                int oc = i / 54; int j = i - oc * 54;
                sm[W1T_OFF + j * 48 + oc] = w1g[i];  // -> [54][48]
            }
            const float* w2g = w2 + s * 2592;       // [6][432]
            for (int i = tid; i < 2592; i += TPB) {
                int oc = i / 432; int j = i - oc * 432;
                sm[W2S_OFF + j * 8 + oc] = w2g[i];   // -> [432][8pad]
            }
            if (tid < 48) sm[B1S_OFF + tid] = b1[s * 48 + tid];
            if (tid < 6)  sm[B2S_OFF + tid] = b2[s * 6 + tid];
        }
        __syncthreads();

        // ---- Phase A: bilinear downsample f -> FSQ quantize -> out (+ rpad) ----
        {
            const float sc = 16.0f / (float)hw;
            float* ob = outb + c_off[s];
            const int n = 6 * npx;
            for (int idx = tid; idx < n; idx += TPB) {
                int c, p;
                if (npx == 1) { c = idx; p = 0; }
                else { c = (int)__umulhi((unsigned)idx, mnpx); p = idx - c * npx; }
                int oy, ox;
                if (hw == 1) { oy = 0; ox = 0; }
                else { oy = (int)__umulhi((unsigned)p, mhw); ox = p - oy * hw; }
                float sy = __fadd_rn(__fmul_rn((float)oy + 0.5f, sc), -0.5f);
                float sx = __fadd_rn(__fmul_rn((float)ox + 0.5f, sc), -0.5f);
                float fy = floorf(sy), fx = floorf(sx);
                float wy = sy - fy,  wx = sx - fx;
                int y0 = (int)fy, x0 = (int)fx;
                int ya = min(max(y0, 0), 15),     yb = min(max(y0 + 1, 0), 15);
                int xa = min(max(x0, 0), 15),     xb = min(max(x0 + 1, 0), 15);
                const float* fc = sm + F_OFF + (c << 8);
                float v00 = fc[ya * 16 + xa], v01 = fc[ya * 16 + xb];
                float v10 = fc[yb * 16 + xa], v11 = fc[yb * 16 + xb];
                float va = __fadd_rn(__fmul_rn(v00, 1.0f - wx), __fmul_rn(v01, wx));
                float vb = __fadd_rn(__fmul_rn(v10, 1.0f - wx), __fmul_rn(v11, wx));
                float v  = __fadd_rn(__fmul_rn(va, 1.0f - wy), __fmul_rn(vb, wy));
                float q;
                if (c < 3) {
                    float bnd = __fadd_rn(__fmul_rn(tanh_xla(v + shift8), halfl8), -0.5f);
                    q = rintf(bnd) * 0.25f;
                } else {
                    float bnd = __fmul_rn(tanh_xla(v), halfl5);
                    q = rintf(bnd) * 0.5f;
                }
                ob[idx] = q;
                if (!last) sm[RPAD_OFF + c * w22 + (oy + 1) * W2 + (ox + 1)] = q;
            }
        }
        if (last) break;
        __syncthreads();

        // ---- conv1 (6->48) + GELU: tasks = (y-pair, oc-group-of-8) ----
        // Per-output fmaf order: ic -> ky -> kx  (bit-identical to R2)
        if (hw == 1) {
            if (tid < 48) {
                float a = 0.0f;
                #pragma unroll
                for (int ic = 0; ic < 6; ic++)
                    a = fmaf(sm[RPAD_OFF + ic * 9 + 4],
                             sm[W1T_OFF + (ic * 9 + 4) * 48 + tid], a);
                sm[HPAD_OFF + tid * 9 + 4] = gelu_exact(a + sm[B1S_OFF + tid]);
            }
        } else {
            const int nq = npx >> 1;
            const int ntask = 6 * nq;
            const uint32_t mnq = c_mnq[s];
            for (int t = tid; t < ntask; t += TPB) {
                int g  = (int)__umulhi((unsigned)t, mnq);
                int q  = t - g * nq;
                int y2 = (int)__umulhi((unsigned)q, mhw);
                int x  = q - y2 * hw;
                int y  = y2 * 2;
                float acc[16];
                #pragma unroll
                for (int i = 0; i < 16; i++) acc[i] = 0.0f;
                const float* wbase = sm + W1T_OFF + g * 8;
                for (int ic = 0; ic < 6; ic++) {
                    const float* rr = sm + RPAD_OFF + ic * w22 + y * W2 + x;
                    float rv[4][3];
                    #pragma unroll
                    for (int kx = 0; kx < 3; kx++) {
                        rv[0][kx] = rr[kx];
                        rv[1][kx] = rr[W2 + kx];
                        rv[2][kx] = rr[2 * W2 + kx];
                        rv[3][kx] = rr[3 * W2 + kx];
                    }
                    const float* wr = wbase + ic * 432;
                    #pragma unroll
                    for (int ky = 0; ky < 3; ky++) {
                        #pragma unroll
                        for (int kx = 0; kx < 3; kx++) {
                            const float* wk = wr + (ky * 3 + kx) * 48;
                            float4 wa = *(const float4*)(wk);
                            float4 wb = *(const float4*)(wk + 4);
                            float v0 = rv[ky][kx];
                            float v1 = rv[ky + 1][kx];
                            acc[0] = fmaf(v0, wa.x, acc[0]);
                            acc[1] = fmaf(v0, wa.y, acc[1]);
                            acc[2] = fmaf(v0, wa.z, acc[2]);
                            acc[3] = fmaf(v0, wa.w, acc[3]);
                            acc[4] = fmaf(v0, wb.x, acc[4]);
                            acc[5] = fmaf(v0, wb.y, acc[5]);
                            acc[6] = fmaf(v0, wb.z, acc[6]);
                            acc[7] = fmaf(v0, wb.w, acc[7]);
                            acc[8]  = fmaf(v1, wa.x, acc[8]);
                            acc[9]  = fmaf(v1, wa.y, acc[9]);
                            acc[10] = fmaf(v1, wa.z, acc[10]);
                            acc[11] = fmaf(v1, wa.w, acc[11]);
                            acc[12] = fmaf(v1, wb.x, acc[12]);
                            acc[13] = fmaf(v1, wb.y, acc[13]);
                            acc[14] = fmaf(v1, wb.z, acc[14]);
                            acc[15] = fmaf(v1, wb.w, acc[15]);
                        }
                    }
                }
                int hp0 = HPAD_OFF + (y + 1) * W2 + (x + 1);
                int oc0 = g * 8;
                #pragma unroll
                for (int j = 0; j < 8; j++) {
                    float bj = sm[B1S_OFF + oc0 + j];
                    sm[hp0 + (oc0 + j) * w22]      = gelu_exact(acc[j] + bj);
                    sm[hp0 + W2 + (oc0 + j) * w22] = gelu_exact(acc[8 + j] + bj);
                }
            }
        }
        __syncthreads();

        // ---- conv2 (48->6): tasks = (y-pair, ic-group-of-SIX) ----
        // 8 partial groups; group arithmetic + reduce order bit-identical to R2
        if (hw == 1) {
            if (tid < 6) {
                float sum = sm[B2S_OFF + tid];
                #pragma unroll
                for (int g = 0; g < 8; g++) {
                    float a = 0.0f;
                    #pragma unroll
                    for (int icl = 0; icl < 6; icl++) {
                        int ic = g * 6 + icl;
                        a = fmaf(sm[HPAD_OFF + ic * 9 + 4],
                                 sm[W2S_OFF + ic * 72 + 32 + tid], a);
                    }
                    sum += a;
                }
                sm[ZBUF_OFF + tid] = sum;
            }
            __syncthreads();
        } else {
            const int nq = npx >> 1;
            const int ntask = 8 * nq;
            const uint32_t mnq = c_mnq[s];
            for (int t = tid; t < ntask; t += TPB) {
                int g  = (int)__umulhi((unsigned)t, mnq);
                int q  = t - g * nq;
                int y2 = (int)__umulhi((unsigned)q, mhw);
                int x  = q - y2 * hw;
                int y  = y2 * 2;
                float acc[12];
                #pragma unroll
                for (int i = 0; i < 12; i++) acc[i] = 0.0f;
                #pragma unroll
                for (int icl = 0; icl < 6; icl++) {
                    int ic = g * 6 + icl;
                    const float* hr = sm + HPAD_OFF + ic * w22 + y * W2 + x;
                    float hv[4][3];
                    #pragma unroll
                    for (int kx = 0; kx < 3; kx++) {
                        hv[0][kx] = hr[kx];
                        hv[1][kx] = hr[W2 + kx];
                        hv[2][kx] = hr[2 * W2 + kx];
                        hv[3][kx] = hr[3 * W2 + kx];
                    }
                    const float* wr = sm + W2S_OFF + ic * 72;
                    #pragma unroll
                    for (int ky = 0; ky < 3; ky++) {
                        #pragma unroll
                        for (int kx = 0; kx < 3; kx++) {
                            const float* wk = wr + (ky * 3 + kx) * 8;
                            float4 wa = *(const float4*)(wk);
                            float2 wb = *(const float2*)(wk + 4);
                            float v0 = hv[ky][kx];
                            float v1 = hv[ky + 1][kx];
                            acc[0] = fmaf(v0, wa.x, acc[0]);
                            acc[1] = fmaf(v0, wa.y, acc[1]);
                            acc[2] = fmaf(v0, wa.z, acc[2]);
                            acc[3] = fmaf(v0, wa.w, acc[3]);
                            acc[4] = fmaf(v0, wb.x, acc[4]);
                            acc[5] = fmaf(v0, wb.y, acc[5]);
                            acc[6]  = fmaf(v1, wa.x, acc[6]);
                            acc[7]  = fmaf(v1, wa.y, acc[7]);
                            acc[8]  = fmaf(v1, wa.z, acc[8]);
                            acc[9]  = fmaf(v1, wa.w, acc[9]);
                            acc[10] = fmaf(v1, wb.x, acc[10]);
                            acc[11] = fmaf(v1, wb.y, acc[11]);
                        }
                    }
                }
                int p0 = y * hw + x;
                float* zp = sm + ZPART_OFF + g * 6 * npx + p0;
                #pragma unroll
                for (int oc = 0; oc < 6; oc++) {
                    zp[oc * npx]      = acc[oc];
                    zp[oc * npx + hw] = acc[6 + oc];
                }
            }
            __syncthreads();

            // reduce 8 partial groups + bias -> zbuf (R2 order)
            {
                const int n = 6 * npx;
                for (int t = tid; t < n; t += TPB) {
                    int oc = (int)__umulhi((unsigned)t, mnpx);
                    int p  = t - oc * npx;
                    float sum = sm[B2S_OFF + oc];
                    #pragma unroll
                    for (int g = 0; g < 8; g++)
                        sum += sm[ZPART_OFF + (g * 6 + oc) * npx + p];
                    sm[ZBUF_OFF + oc * npx + p] = sum;
                }
            }
            __syncthreads();
        }

        // ---- bilinear upsample zbuf -> 16x16, subtract from f ----
        {
            const float sc2 = (float)hw / 16.0f;
            const int hm = hw - 1;
            for (int idx = tid; idx < 1536; idx += TPB) {
                int c = idx >> 8, p = idx & 255;
                int oy = p >> 4, ox = p & 15;
                float sy = __fadd_rn(__fmul_rn((float)oy + 0.5f, sc2), -0.5f);
                float sx = __fadd_rn(__fmul_rn((float)ox + 0.5f, sc2), -0.5f);
                float fy = floorf(sy), fx = floorf(sx);
                float wy = sy - fy,  wx = sx - fx;
                int y0 = (int)fy, x0 = (int)fx;
                int ya = min(max(y0, 0), hm), yb = min(max(y0 + 1, 0), hm);
                int xa = min(max(x0, 0), hm), xb = min(max(x0 + 1, 0), hm);
                const float* zc = sm + ZBUF_OFF + c * npx;
                float v00 = zc[ya * hw + xa], v01 = zc[ya * hw + xb];
                float v10 = zc[yb * hw + xa], v11 = zc[yb * hw + xb];
                float va = __fadd_rn(__fmul_rn(v00, 1.0f - wx), __fmul_rn(v01, wx));
                float vb = __fadd_rn(__fmul_rn(v10, 1.0f - wx), __fmul_rn(v11, wx));
                float v  = __fadd_rn(__fmul_rn(va, 1.0f - wy), __fmul_rn(vb, wy));
                sm[F_OFF + idx] -= v;
            }
        }
        __syncthreads();
    }
}

extern "C" void kernel_launch(void* const* d_in, const int* in_sizes, int n_in,
                              void* d_out, int out_size) {
    const float* latents = (const float*)d_in[0];
    const float* w1 = (const float*)d_in[1];
    const float* b1 = (const float*)d_in[2];
    const float* w2 = (const float*)d_in[3];
    const float* b2 = (const float*)d_in[4];
    float* out = (float*)d_out;
    int B = in_sizes[0] / 1536;
    cudaFuncSetAttribute(var_tok_kernel,
                         cudaFuncAttributeMaxDynamicSharedMemorySize, SMEM_BYTES);
    var_tok_kernel<<<B, TPB, SMEM_BYTES>>>(latents, w1, b1, w2, b2, out);
}

// round 8
// speedup vs baseline: 1.3142x; 1.1405x over previous
#include <cuda_runtime.h>
#include <math.h>
#include <stdint.h>

#define TPB 256

// shared-memory float offsets (same layout as the passing R2/R7 kernel)
#define F_OFF     0        // 6*16*16  = 1536
#define RPAD_OFF  1536     // 6*14*14  = 1176
#define HPAD_OFF  2712     // 48*14*14 = 9408
#define ZPART_OFF 12120    // 8*6*144  = 6912
#define ZBUF_OFF  19032    // 6*144    = 864
#define W1T_OFF   19896    // 54*48    = 2592  (16B aligned)
#define W2S_OFF   22488    // 432*8    = 3456  (16B aligned)
#define B1S_OFF   25944    // 48
#define B2S_OFF   25992    // 8
#define SMEM_FLOATS 26000
#define SMEM_BYTES (SMEM_FLOATS * 4)

__constant__ int      c_hw[8]   = {1, 2, 4, 6, 8, 10, 12, 16};
__constant__ int      c_off[8]  = {0, 6, 30, 126, 342, 726, 1326, 2190};
// ceil(2^32/d); sentinel 0 for d==1
__constant__ uint32_t c_mhw[8]  = {0u, 2147483648u, 1073741824u, 715827883u,
                                   536870912u, 429496730u, 357913942u, 268435456u};
__constant__ uint32_t c_mnpx[8] = {0u, 1073741824u, 268435456u, 119304648u,
                                   67108864u, 42949673u, 29826162u, 16777216u};
// nq = npx/2: {-,2,8,18,32,50,72,-}
__constant__ uint32_t c_mnq[8]  = {0u, 2147483648u, 536870912u, 238609295u,
                                   134217728u, 85899346u, 59652324u, 0u};

// XLA's fp32 tanh rational approximation
__device__ __forceinline__ float tanh_xla(float x) {
    float cx = fminf(fmaxf(x, -7.90531110763549805f), 7.90531110763549805f);
    float x2 = cx * cx;
    float np_ = fmaf(-2.76076847742355e-16f, x2, 2.00018790482477e-13f);
    np_ = fmaf(np_, x2, -8.60467152213735e-11f);
    np_ = fmaf(np_, x2, 5.12229709037114e-08f);
    np_ = fmaf(np_, x2, 1.48572235717979e-05f);
    np_ = fmaf(np_, x2, 6.37261928875436e-04f);
    np_ = fmaf(np_, x2, 4.89352455891786e-03f);
    float num = cx * np_;
    float dp_ = fmaf(1.19825839466702e-06f, x2, 1.18534705686654e-04f);
    dp_ = fmaf(dp_, x2, 2.26843463243900e-03f);
    dp_ = fmaf(dp_, x2, 4.89352518554385e-03f);
    float r = num / dp_;
    return (fabsf(x) < 0.0004f) ? x : r;
}

__device__ __forceinline__ float gelu_exact(float h) {
    return 0.5f * h * (1.0f + erff(h * 0.70710678118654752f));
}

__global__ void __launch_bounds__(TPB) var_tok_kernel(
    const float* __restrict__ latents, const float* __restrict__ w1,
    const float* __restrict__ b1, const float* __restrict__ w2,
    const float* __restrict__ b2, float* __restrict__ out)
{
    extern __shared__ float sm[];
    const int tid = threadIdx.x;

    const float halfl8 = (8.0f - 1.0f) * (1.0f + 1e-3f) / 2.0f;
    const float shift8 = atanhf(0.5f / halfl8);
    const float halfl5 = (5.0f - 1.0f) * (1.0f + 1e-3f) / 2.0f;

    const float* lat = latents + (size_t)blockIdx.x * 1536;
    float* outb = out + (size_t)blockIdx.x * 3726;

    for (int i = tid; i < 1536; i += TPB) sm[F_OFF + i] = lat[i];

    for (int s = 0; s < 8; s++) {
        const int hw  = c_hw[s];
        const int npx = hw * hw;
        const int W2  = hw + 2;
        const int w22 = W2 * W2;
        const uint32_t mhw  = c_mhw[s];
        const uint32_t mnpx = c_mnpx[s];
        const bool last = (s == 7);

        // ---- stage 0: zero padded buffers, stage reordered weights ----
        if (!last) {
            if (hw > 1) {
                for (int i = tid; i < 6 * w22;  i += TPB) sm[RPAD_OFF + i] = 0.0f;
                for (int i = tid; i < 48 * w22; i += TPB) sm[HPAD_OFF + i] = 0.0f;
            }
            const float* w1g = w1 + s * 2592;       // [48][54]
            for (int i = tid; i < 2592; i += TPB) {
                int oc = i / 54; int j = i - oc * 54;
                sm[W1T_OFF + j * 48 + oc] = w1g[i];  // -> [54][48]
            }
            const float* w2g = w2 + s * 2592;       // [6][432]
            for (int i = tid; i < 2592; i += TPB) {
                int oc = i / 432; int j = i - oc * 432;
                sm[W2S_OFF + j * 8 + oc] = w2g[i];   // -> [432][8pad]
            }
            if (tid < 48) sm[B1S_OFF + tid] = b1[s * 48 + tid];
            if (tid < 6)  sm[B2S_OFF + tid] = b2[s * 6 + tid];
        }
        __syncthreads();

        // ---- Phase A: bilinear downsample f -> FSQ quantize -> out (+ rpad) ----
        {
            const float sc = 16.0f / (float)hw;
            float* ob = outb + c_off[s];
            const int n = 6 * npx;
            for (int idx = tid; idx < n; idx += TPB) {
                int c, p;
                if (npx == 1) { c = idx; p = 0; }
                else { c = (int)__umulhi((unsigned)idx, mnpx); p = idx - c * npx; }
                int oy, ox;
                if (hw == 1) { oy = 0; ox = 0; }
                else { oy = (int)__umulhi((unsigned)p, mhw); ox = p - oy * hw; }
                float sy = __fadd_rn(__fmul_rn((float)oy + 0.5f, sc), -0.5f);
                float sx = __fadd_rn(__fmul_rn((float)ox + 0.5f, sc), -0.5f);
                float fy = floorf(sy), fx = floorf(sx);
                float wy = sy - fy,  wx = sx - fx;
                int y0 = (int)fy, x0 = (int)fx;
                int ya = min(max(y0, 0), 15),     yb = min(max(y0 + 1, 0), 15);
                int xa = min(max(x0, 0), 15),     xb = min(max(x0 + 1, 0), 15);
                const float* fc = sm + F_OFF + (c << 8);
                float v00 = fc[ya * 16 + xa], v01 = fc[ya * 16 + xb];
                float v10 = fc[yb * 16 + xa], v11 = fc[yb * 16 + xb];
                float va = __fadd_rn(__fmul_rn(v00, 1.0f - wx), __fmul_rn(v01, wx));
                float vb = __fadd_rn(__fmul_rn(v10, 1.0f - wx), __fmul_rn(v11, wx));
                float v  = __fadd_rn(__fmul_rn(va, 1.0f - wy), __fmul_rn(vb, wy));
                float q;
                if (c < 3) {
                    float bnd = __fadd_rn(__fmul_rn(tanh_xla(v + shift8), halfl8), -0.5f);
                    q = rintf(bnd) * 0.25f;
                } else {
                    float bnd = __fmul_rn(tanh_xla(v), halfl5);
                    q = rintf(bnd) * 0.5f;
                }
                ob[idx] = q;
                if (!last) sm[RPAD_OFF + c * w22 + (oy + 1) * W2 + (ox + 1)] = q;
            }
        }
        if (last) break;
        __syncthreads();

        // ---- conv1 (6->48) + GELU: tasks = (y-pair, oc-group-of-8) ----
        // Per-output fmaf order: ic -> ky -> kx  (bit-identical to R2)
        if (hw == 1) {
            if (tid < 48) {
                float a = 0.0f;
                #pragma unroll
                for (int ic = 0; ic < 6; ic++)
                    a = fmaf(sm[RPAD_OFF + ic * 9 + 4],
                             sm[W1T_OFF + (ic * 9 + 4) * 48 + tid], a);
                sm[HPAD_OFF + tid * 9 + 4] = gelu_exact(a + sm[B1S_OFF + tid]);
            }
        } else {
            const int nq = npx >> 1;
            const int ntask = 6 * nq;
            const uint32_t mnq = c_mnq[s];
            for (int t = tid; t < ntask; t += TPB) {
                int g  = (int)__umulhi((unsigned)t, mnq);
                int q  = t - g * nq;
                int y2 = (int)__umulhi((unsigned)q, mhw);
                int x  = q - y2 * hw;
                int y  = y2 * 2;
                float acc[16];
                #pragma unroll
                for (int i = 0; i < 16; i++) acc[i] = 0.0f;
                const float* wbase = sm + W1T_OFF + g * 8;
                for (int ic = 0; ic < 6; ic++) {
                    const float* rr = sm + RPAD_OFF + ic * w22 + y * W2 + x;
                    float rv[4][3];
                    #pragma unroll
                    for (int kx = 0; kx < 3; kx++) {
                        rv[0][kx] = rr[kx];
                        rv[1][kx] = rr[W2 + kx];
                        rv[2][kx] = rr[2 * W2 + kx];
                        rv[3][kx] = rr[3 * W2 + kx];
                    }
                    const float* wr = wbase + ic * 432;
                    #pragma unroll
                    for (int ky = 0; ky < 3; ky++) {
                        #pragma unroll
                        for (int kx = 0; kx < 3; kx++) {
                            const float* wk = wr + (ky * 3 + kx) * 48;
                            float4 wa = *(const float4*)(wk);
                            float4 wb = *(const float4*)(wk + 4);
                            float v0 = rv[ky][kx];
                            float v1 = rv[ky + 1][kx];
                            acc[0] = fmaf(v0, wa.x, acc[0]);
                            acc[1] = fmaf(v0, wa.y, acc[1]);
                            acc[2] = fmaf(v0, wa.z, acc[2]);
                            acc[3] = fmaf(v0, wa.w, acc[3]);
                            acc[4] = fmaf(v0, wb.x, acc[4]);
                            acc[5] = fmaf(v0, wb.y, acc[5]);
                            acc[6] = fmaf(v0, wb.z, acc[6]);
                            acc[7] = fmaf(v0, wb.w, acc[7]);
                            acc[8]  = fmaf(v1, wa.x, acc[8]);
                            acc[9]  = fmaf(v1, wa.y, acc[9]);
                            acc[10] = fmaf(v1, wa.z, acc[10]);
                            acc[11] = fmaf(v1, wa.w, acc[11]);
                            acc[12] = fmaf(v1, wb.x, acc[12]);
                            acc[13] = fmaf(v1, wb.y, acc[13]);
                            acc[14] = fmaf(v1, wb.z, acc[14]);
                            acc[15] = fmaf(v1, wb.w, acc[15]);
                        }
                    }
                }
                int hp0 = HPAD_OFF + (y + 1) * W2 + (x + 1);
                int oc0 = g * 8;
                #pragma unroll
                for (int j = 0; j < 8; j++) {
                    float bj = sm[B1S_OFF + oc0 + j];
                    sm[hp0 + (oc0 + j) * w22]      = gelu_exact(acc[j] + bj);
                    sm[hp0 + W2 + (oc0 + j) * w22] = gelu_exact(acc[8 + j] + bj);
                }
            }
        }
        __syncthreads();

        // ---- conv2 (48->6): tasks = (y-pair, ic-group-of-SIX) ----
        // 8 partial groups; group arithmetic + reduce order bit-identical to R2
        if (hw == 1) {
            if (tid < 6) {
                float sum = sm[B2S_OFF + tid];
                #pragma unroll
                for (int g = 0; g < 8; g++) {
                    float a = 0.0f;
                    #pragma unroll
                    for (int icl = 0; icl < 6; icl++) {
                        int ic = g * 6 + icl;
                        a = fmaf(sm[HPAD_OFF + ic * 9 + 4],
                                 sm[W2S_OFF + ic * 72 + 32 + tid], a);
                    }
                    sum += a;
                }
                sm[ZBUF_OFF + tid] = sum;
            }
            __syncthreads();
        } else {
            const int nq = npx >> 1;
            const int ntask = 8 * nq;
            const uint32_t mnq = c_mnq[s];
            for (int t = tid; t < ntask; t += TPB) {
                int g  = (int)__umulhi((unsigned)t, mnq);
                int q  = t - g * nq;
                int y2 = (int)__umulhi((unsigned)q, mhw);
                int x  = q - y2 * hw;
                int y  = y2 * 2;
                float acc[12];
                #pragma unroll
                for (int i = 0; i < 12; i++) acc[i] = 0.0f;
                #pragma unroll
                for (int icl = 0; icl < 6; icl++) {
                    int ic = g * 6 + icl;
                    const float* hr = sm + HPAD_OFF + ic * w22 + y * W2 + x;
                    float hv[4][3];
                    #pragma unroll
                    for (int kx = 0; kx < 3; kx++) {
                        hv[0][kx] = hr[kx];
                        hv[1][kx] = hr[W2 + kx];
                        hv[2][kx] = hr[2 * W2 + kx];
                        hv[3][kx] = hr[3 * W2 + kx];
                    }
                    const float* wr = sm + W2S_OFF + ic * 72;
                    #pragma unroll
                    for (int ky = 0; ky < 3; ky++) {
                        #pragma unroll
                        for (int kx = 0; kx < 3; kx++) {
                            const float* wk = wr + (ky * 3 + kx) * 8;
                            float4 wa = *(const float4*)(wk);
                            float2 wb = *(const float2*)(wk + 4);
                            float v0 = hv[ky][kx];
                            float v1 = hv[ky + 1][kx];
                            acc[0] = fmaf(v0, wa.x, acc[0]);
                            acc[1] = fmaf(v0, wa.y, acc[1]);
                            acc[2] = fmaf(v0, wa.z, acc[2]);
                            acc[3] = fmaf(v0, wa.w, acc[3]);
                            acc[4] = fmaf(v0, wb.x, acc[4]);
                            acc[5] = fmaf(v0, wb.y, acc[5]);
                            acc[6]  = fmaf(v1, wa.x, acc[6]);
                            acc[7]  = fmaf(v1, wa.y, acc[7]);
                            acc[8]  = fmaf(v1, wa.z, acc[8]);
                            acc[9]  = fmaf(v1, wa.w, acc[9]);
                            acc[10] = fmaf(v1, wb.x, acc[10]);
                            acc[11] = fmaf(v1, wb.y, acc[11]);
                        }
                    }
                }
                int p0 = y * hw + x;
                float* zp = sm + ZPART_OFF + g * 6 * npx + p0;
                #pragma unroll
                for (int oc = 0; oc < 6; oc++) {
                    zp[oc * npx]      = acc[oc];
                    zp[oc * npx + hw] = acc[6 + oc];
                }
            }
            __syncthreads();

            // reduce 8 partial groups + bias -> zbuf (R2 order)
            {
                const int n = 6 * npx;
                for (int t = tid; t < n; t += TPB) {
                    int oc = (int)__umulhi((unsigned)t, mnpx);
                    int p  = t - oc * npx;
                    float sum = sm[B2S_OFF + oc];
                    #pragma unroll
                    for (int g = 0; g < 8; g++)
                        sum += sm[ZPART_OFF + (g * 6 + oc) * npx + p];
                    sm[ZBUF_OFF + oc * npx + p] = sum;
                }
            }
            __syncthreads();
        }

        // ---- bilinear upsample zbuf -> 16x16, subtract from f ----
        {
            const float sc2 = (float)hw / 16.0f;
            const int hm = hw - 1;
            for (int idx = tid; idx < 1536; idx += TPB) {
                int c = idx >> 8, p = idx & 255;
                int oy = p >> 4, ox = p & 15;
                float sy = __fadd_rn(__fmul_rn((float)oy + 0.5f, sc2), -0.5f);
                float sx = __fadd_rn(__fmul_rn((float)ox + 0.5f, sc2), -0.5f);
                float fy = floorf(sy), fx = floorf(sx);
                float wy = sy - fy,  wx = sx - fx;
                int y0 = (int)fy, x0 = (int)fx;
                int ya = min(max(y0, 0), hm), yb = min(max(y0 + 1, 0), hm);
                int xa = min(max(x0, 0), hm), xb = min(max(x0 + 1, 0), hm);
                const float* zc = sm + ZBUF_OFF + c * npx;
                float v00 = zc[ya * hw + xa], v01 = zc[ya * hw + xb];
                float v10 = zc[yb * hw + xa], v11 = zc[yb * hw + xb];
                float va = __fadd_rn(__fmul_rn(v00, 1.0f - wx), __fmul_rn(v01, wx));
                float vb = __fadd_rn(__fmul_rn(v10, 1.0f - wx), __fmul_rn(v11, wx));
                float v  = __fadd_rn(__fmul_rn(va, 1.0f - wy), __fmul_rn(vb, wy));
                sm[F_OFF + idx] -= v;
            }
        }
        __syncthreads();
    }
}

extern "C" void kernel_launch(void* const* d_in, const int* in_sizes, int n_in,
                              void* d_out, int out_size) {
    const float* latents = (const float*)d_in[0];
    const float* w1 = (const float*)d_in[1];
    const float* b1 = (const float*)d_in[2];
    const float* w2 = (const float*)d_in[3];
    const float* b2 = (const float*)d_in[4];
    float* out = (float*)d_out;
    int B = in_sizes[0] / 1536;
    cudaFuncSetAttribute(var_tok_kernel,
                         cudaFuncAttributeMaxDynamicSharedMemorySize, SMEM_BYTES);
    var_tok_kernel<<<B, TPB, SMEM_BYTES>>>(latents, w1, b1, w2, b2, out);
}